// round 13
// baseline (speedup 1.0000x reference)
#include <cuda_runtime.h>
#include <cuda_bf16.h>
#include <float.h>

#define NS 512
#define EMB 256

// scratch (device globals — no allocation allowed; zero-initialized at load,
// and reset by the finalize path after every run so graph replays are clean)
__device__ float    g_G[NS * NS];   // gram matrix E·E^T
__device__ float    g_diag[NS];     // diagonal = squared norms
__device__ double   g_loss;
__device__ int      g_count;
__device__ int      g_done;
__device__ unsigned g_barrier;

// Single fused kernel. Phase 1: blocks 0..255 compute one 32x32 tile of G
// (proven 2x2-register-blocked GEMM). All 512 blocks meanwhile build their
// positive-pair list and prefetch the first rand_u batch (independent of G).
// Device-wide flag barrier (all blocks co-resident by __launch_bounds__),
// then the pipelined random-hard-negative argmax per anchor.
__global__ void __launch_bounds__(256, 4)
fused_kernel(const float* __restrict__ E,
             const float* __restrict__ R,
             const int* __restrict__ lab,
             float* __restrict__ out, int out_size) {
    const int b = blockIdx.x;
    const int t = threadIdx.x;
    const int wid = t >> 5, lane = t & 31;

    __shared__ union {
        struct { float As[32][34]; float Bs[32][34]; } g;   // phase 1
        struct { float Drow[NS]; float adj[NS]; } p;        // phase 2
    } u;
    __shared__ int labs[NS];
    __shared__ int pos[NS];
    __shared__ int m;

    // ───────── phase 1: G tile (blocks 0..255 only) ─────────
    if (b < 256) {
        const int tx = t & 15, ty = t >> 4;
        const int r0 = (b >> 4) * 32, c0 = (b & 15) * 32;
        const int lrow = t >> 3, lcol = (t & 7) * 4;
        float acc00 = 0.f, acc01 = 0.f, acc10 = 0.f, acc11 = 0.f;
        for (int k0 = 0; k0 < EMB; k0 += 32) {
            float4 av = *(const float4*)&E[(r0 + lrow) * EMB + k0 + lcol];
            float4 bv = *(const float4*)&E[(c0 + lrow) * EMB + k0 + lcol];
            __syncthreads();
            u.g.As[lrow][lcol + 0] = av.x; u.g.As[lrow][lcol + 1] = av.y;
            u.g.As[lrow][lcol + 2] = av.z; u.g.As[lrow][lcol + 3] = av.w;
            u.g.Bs[lrow][lcol + 0] = bv.x; u.g.Bs[lrow][lcol + 1] = bv.y;
            u.g.Bs[lrow][lcol + 2] = bv.z; u.g.Bs[lrow][lcol + 3] = bv.w;
            __syncthreads();
#pragma unroll
            for (int k = 0; k < 32; k += 2) {
                float2 a0 = *(const float2*)&u.g.As[ty][k];
                float2 a1 = *(const float2*)&u.g.As[ty + 16][k];
                float2 b0 = *(const float2*)&u.g.Bs[tx][k];
                float2 b1 = *(const float2*)&u.g.Bs[tx + 16][k];
                acc00 += a0.x * b0.x + a0.y * b0.y;
                acc01 += a0.x * b1.x + a0.y * b1.y;
                acc10 += a1.x * b0.x + a1.y * b0.y;
                acc11 += a1.x * b1.x + a1.y * b1.y;
            }
        }
        int r_a = r0 + ty, r_b = r0 + ty + 16;
        int c_a = c0 + tx, c_b = c0 + tx + 16;
        g_G[r_a * NS + c_a] = acc00;
        g_G[r_a * NS + c_b] = acc01;
        g_G[r_b * NS + c_a] = acc10;
        g_G[r_b * NS + c_b] = acc11;
        if (r_a == c_a) g_diag[r_a] = acc00;
        if (r_a == c_b) g_diag[r_a] = acc01;
        if (r_b == c_a) g_diag[r_b] = acc10;
        if (r_b == c_b) g_diag[r_b] = acc11;
    }

    // ───────── pair prologue A: labels + positive list (no G needed) ─────────
    const int i = b;
    const int li = lab[i];
    if (t == 0) m = 0;
    __syncthreads();
    for (int n = t; n < NS; n += 256) labs[n] = lab[n];
    __syncthreads();
    for (int n = i + 1 + t; n < NS; n += 256)
        if (labs[n] == li) pos[atomicAdd(&m, 1)] = n;
    __syncthreads();
    const int mm = m;
    const size_t ibase = (size_t)i * NS * NS;

    // prefetch the FIRST batch of rand_u rows — overlaps phase-1 GEMM/barrier
    int p = wid;
    float4 r0v, r1v, r2v, r3v;
    if (p < mm) {
        const float4* R4 = (const float4*)(R + ibase + (size_t)pos[p] * NS);
        r0v = R4[lane]; r1v = R4[lane + 32];
        r2v = R4[lane + 64]; r3v = R4[lane + 96];
    }

    // ───────── device-wide barrier (all 512 blocks co-resident) ─────────
    if (t == 0) {
        __threadfence();
        atomicAdd(&g_barrier, 1u);
        while (*(volatile unsigned*)&g_barrier < (unsigned)gridDim.x) {}
    }
    __syncthreads();

    // ───────── pair prologue B: D row + thresholds (needs G) ─────────
    const float di = g_diag[i];
    for (int n = t; n < NS; n += 256) {
        float D = di + g_diag[n] - 2.0f * g_G[i * NS + n];
        u.p.Drow[n] = D;
        u.p.adj[n] = (labs[n] == li) ? FLT_MAX : (D - 3.0f);
    }
    __syncthreads();

    const float4* __restrict__ adj4 = (const float4*)u.p.adj;
    const float4 a0 = adj4[lane];
    const float4 a1 = adj4[lane + 32];
    const float4 a2 = adj4[lane + 64];
    const float4 a3 = adj4[lane + 96];
    const int nb0 = lane * 4;

    double wloss = 0.0;
    int    wcount = 0;

    while (p < mm) {
        const int pn = p + 8;
        float4 s0, s1, s2, s3;
        if (pn < mm) {                        // prefetch next pair's row
            const float4* R4n = (const float4*)(R + ibase + (size_t)pos[pn] * NS);
            s0 = R4n[lane]; s1 = R4n[lane + 32];
            s2 = R4n[lane + 64]; s3 = R4n[lane + 96];
        }
        const float Dij = u.p.Drow[pos[p]];

        float bs = -1.0f;                     // scores in [0,1); -1 = none
        int   bi = 0x7fffffff;
        // n ascending within lane + strict > ⇒ first-occurrence kept
        if (Dij > a0.x && r0v.x > bs) { bs = r0v.x; bi = nb0 + 0; }
        if (Dij > a0.y && r0v.y > bs) { bs = r0v.y; bi = nb0 + 1; }
        if (Dij > a0.z && r0v.z > bs) { bs = r0v.z; bi = nb0 + 2; }
        if (Dij > a0.w && r0v.w > bs) { bs = r0v.w; bi = nb0 + 3; }
        if (Dij > a1.x && r1v.x > bs) { bs = r1v.x; bi = nb0 + 128; }
        if (Dij > a1.y && r1v.y > bs) { bs = r1v.y; bi = nb0 + 129; }
        if (Dij > a1.z && r1v.z > bs) { bs = r1v.z; bi = nb0 + 130; }
        if (Dij > a1.w && r1v.w > bs) { bs = r1v.w; bi = nb0 + 131; }
        if (Dij > a2.x && r2v.x > bs) { bs = r2v.x; bi = nb0 + 256; }
        if (Dij > a2.y && r2v.y > bs) { bs = r2v.y; bi = nb0 + 257; }
        if (Dij > a2.z && r2v.z > bs) { bs = r2v.z; bi = nb0 + 258; }
        if (Dij > a2.w && r2v.w > bs) { bs = r2v.w; bi = nb0 + 259; }
        if (Dij > a3.x && r3v.x > bs) { bs = r3v.x; bi = nb0 + 384; }
        if (Dij > a3.y && r3v.y > bs) { bs = r3v.y; bi = nb0 + 385; }
        if (Dij > a3.z && r3v.z > bs) { bs = r3v.z; bi = nb0 + 386; }
        if (Dij > a3.w && r3v.w > bs) { bs = r3v.w; bi = nb0 + 387; }

        // warp argmax, tie-break toward smaller index
        for (int off = 16; off; off >>= 1) {
            float os = __shfl_down_sync(0xffffffffu, bs, off);
            int   oi = __shfl_down_sync(0xffffffffu, bi, off);
            if (os > bs || (os == bs && oi < bi)) { bs = os; bi = oi; }
        }
        if (lane == 0 && bs >= -0.5f) {
            wloss += (double)(Dij - u.p.Drow[bi] + 3.0f);
            wcount += 1;
        }

        p = pn;
        r0v = s0; r1v = s1; r2v = s2; r3v = s3;
    }
    if (lane == 0 && wcount > 0) {
        atomicAdd(&g_loss, wloss);
        atomicAdd(&g_count, wcount);
    }
    __syncthreads();

    // fused finalize: last block writes output and resets state for replay
    if (t == 0) {
        __threadfence();
        int prev = atomicAdd(&g_done, 1);
        if (prev == (int)gridDim.x - 1) {
            double l = atomicAdd(&g_loss, 0.0);
            int    c = atomicAdd(&g_count, 0);
            int denom = c > 0 ? c : 1;
            out[0] = (float)(l / (double)denom);
            if (out_size > 1) out[1] = (float)c;
            for (int k = 2; k < out_size; k++) out[k] = 0.0f;
            // reset for next graph replay
            g_loss = 0.0; g_count = 0; g_done = 0; g_barrier = 0u;
        }
    }
}

extern "C" void kernel_launch(void* const* d_in, const int* in_sizes, int n_in,
                              void* d_out, int out_size) {
    const float* E   = (const float*)d_in[0];   // embeddings [512,256] f32
    const int*   lab = (const int*)d_in[1];     // labels [512] i32
    const float* R   = (const float*)d_in[2];   // rand_u [512,512,512] f32
    float* out = (float*)d_out;

    fused_kernel<<<NS, 256>>>(E, R, lab, out, out_size);
}

// round 16
// speedup vs baseline: 1.0816x; 1.0816x over previous
#include <cuda_runtime.h>
#include <cuda_bf16.h>
#include <float.h>

#define NS 512
#define EMB 256

// scratch (device globals — no allocation allowed)
__device__ float  g_G[NS * NS];     // gram matrix E·E^T
__device__ float  g_diag[NS];       // diagonal = squared norms
__device__ double g_loss;
__device__ int    g_count;
__device__ int    g_done;

// Kernel 1: G = E·E^T, 32x32 tiles, 2x2 register blocking (proven R9/R12).
__global__ void dot_kernel(const float* __restrict__ E) {
    if (blockIdx.x == 0 && blockIdx.y == 0 && threadIdx.x == 0 && threadIdx.y == 0) {
        g_loss = 0.0; g_count = 0; g_done = 0;
    }
    __shared__ float As[32][34];
    __shared__ float Bs[32][34];
    const int tx = threadIdx.x;            // 0..15
    const int ty = threadIdx.y;            // 0..15
    const int tid = ty * 16 + tx;
    const int r0 = blockIdx.y * 32;
    const int c0 = blockIdx.x * 32;
    const int lrow = tid >> 3;             // 0..31
    const int lcol = (tid & 7) * 4;        // 0,4,...,28

    float acc00 = 0.f, acc01 = 0.f, acc10 = 0.f, acc11 = 0.f;

    for (int k0 = 0; k0 < EMB; k0 += 32) {
        float4 av = *(const float4*)&E[(r0 + lrow) * EMB + k0 + lcol];
        float4 bv = *(const float4*)&E[(c0 + lrow) * EMB + k0 + lcol];
        As[lrow][lcol + 0] = av.x; As[lrow][lcol + 1] = av.y;
        As[lrow][lcol + 2] = av.z; As[lrow][lcol + 3] = av.w;
        Bs[lrow][lcol + 0] = bv.x; Bs[lrow][lcol + 1] = bv.y;
        Bs[lrow][lcol + 2] = bv.z; Bs[lrow][lcol + 3] = bv.w;
        __syncthreads();
#pragma unroll
        for (int k = 0; k < 32; k += 2) {
            float2 a0 = *(const float2*)&As[ty][k];
            float2 a1 = *(const float2*)&As[ty + 16][k];
            float2 b0 = *(const float2*)&Bs[tx][k];
            float2 b1 = *(const float2*)&Bs[tx + 16][k];
            acc00 += a0.x * b0.x + a0.y * b0.y;
            acc01 += a0.x * b1.x + a0.y * b1.y;
            acc10 += a1.x * b0.x + a1.y * b0.y;
            acc11 += a1.x * b1.x + a1.y * b1.y;
        }
        __syncthreads();
    }

    int r_a = r0 + ty, r_b = r0 + ty + 16;
    int c_a = c0 + tx, c_b = c0 + tx + 16;
    g_G[r_a * NS + c_a] = acc00;
    g_G[r_a * NS + c_b] = acc01;
    g_G[r_b * NS + c_a] = acc10;
    g_G[r_b * NS + c_b] = acc11;
    if (r_a == c_a) g_diag[r_a] = acc00;
    if (r_a == c_b) g_diag[r_a] = acc01;
    if (r_b == c_a) g_diag[r_b] = acc10;
    if (r_b == c_b) g_diag[r_b] = acc11;
}

// Kernel 2: TWO blocks per anchor (grid 1024). Positive-pair list built by
// DETERMINISTIC ballot compaction (ascending j, identical in both blocks),
// so the index-range partition between the two blocks is exact.
__global__ void __launch_bounds__(256)
pair_kernel(const float* __restrict__ R,
            const int* __restrict__ lab,
            float* __restrict__ out, int out_size) {
    const int b = blockIdx.x;
    const int i = b >> 1;
    const int half = b & 1;
    const int t = threadIdx.x;
    const int wid = t >> 5, lane = t & 31;

    __shared__ float Drow[NS];   // raw G row, then D row (in place)
    __shared__ float diag_s[NS];
    __shared__ float adj[NS];    // labs[n]==li ? +INF : Drow[n]-MARGIN
    __shared__ int   labs[NS];
    __shared__ int   pos[NS];    // positive-j list, ascending (deterministic)
    __shared__ int   ccnt[16];   // per-32-chunk match counts

    // split prologue: two independent MLP-2 load chains
    if (t < 128) {
        *(int4*)&labs[t * 4]     = *(const int4*)&lab[t * 4];
        *(float4*)&diag_s[t * 4] = *(const float4*)&g_diag[t * 4];
    } else {
        int n4 = (t - 128) * 4;
        *(float4*)&Drow[n4] = *(const float4*)&g_G[i * NS + n4];
    }
    __syncthreads();

    const int   li = labs[i];
    const float di = diag_s[i];
    for (int n = t; n < NS; n += 256) {
        float D = di + diag_s[n] - 2.0f * Drow[n];
        Drow[n] = D;
        adj[n]  = (labs[n] == li) ? FLT_MAX : (D - 3.0f);
    }

    // deterministic stable compaction: warp wid owns chunks 2*wid, 2*wid+1
    const int n0 = wid * 64 + lane;
    const int n1 = n0 + 32;
    const bool p0 = (n0 > i) && (labs[n0] == li);
    const bool p1 = (n1 > i) && (labs[n1] == li);
    const unsigned m0 = __ballot_sync(0xffffffffu, p0);
    const unsigned m1 = __ballot_sync(0xffffffffu, p1);
    if (lane == 0) { ccnt[2 * wid] = __popc(m0); ccnt[2 * wid + 1] = __popc(m1); }
    __syncthreads();
    int off0 = 0, off1 = 0, mm = 0;
#pragma unroll
    for (int k = 0; k < 16; k++) {
        int c = ccnt[k];
        if (k < 2 * wid)     off0 += c;
        if (k < 2 * wid + 1) off1 += c;
        mm += c;
    }
    const unsigned below = (1u << lane) - 1u;
    if (p0) pos[off0 + __popc(m0 & below)] = n0;
    if (p1) pos[off1 + __popc(m1 & below)] = n1;
    __syncthreads();

    double wloss = 0.0;
    int    wcount = 0;

    if (mm > 0) {
        const float4* __restrict__ adj4 = (const float4*)adj;
        const float4 a0 = adj4[lane];
        const float4 a1 = adj4[lane + 32];
        const float4 a2 = adj4[lane + 64];
        const float4 a3 = adj4[lane + 96];
        const int nb0 = lane * 4;
        const size_t ibase = (size_t)i * NS * NS;

        int p = half * 8 + wid;              // this block's pair slots
        float4 r0v, r1v, r2v, r3v;
        if (p < mm) {
            const float4* R4 = (const float4*)(R + ibase + (size_t)pos[p] * NS);
            r0v = R4[lane]; r1v = R4[lane + 32];
            r2v = R4[lane + 64]; r3v = R4[lane + 96];
        }
        while (p < mm) {
            const int pn = p + 16;
            float4 s0, s1, s2, s3;
            if (pn < mm) {                   // prefetch next pair's row
                const float4* R4n = (const float4*)(R + ibase + (size_t)pos[pn] * NS);
                s0 = R4n[lane]; s1 = R4n[lane + 32];
                s2 = R4n[lane + 64]; s3 = R4n[lane + 96];
            }
            const float Dij = Drow[pos[p]];

            float bs = -1.0f;                // scores in [0,1); -1 = none
            int   bi = 0x7fffffff;
            // n ascending within lane + strict > ⇒ first-occurrence kept
            if (Dij > a0.x && r0v.x > bs) { bs = r0v.x; bi = nb0 + 0; }
            if (Dij > a0.y && r0v.y > bs) { bs = r0v.y; bi = nb0 + 1; }
            if (Dij > a0.z && r0v.z > bs) { bs = r0v.z; bi = nb0 + 2; }
            if (Dij > a0.w && r0v.w > bs) { bs = r0v.w; bi = nb0 + 3; }
            if (Dij > a1.x && r1v.x > bs) { bs = r1v.x; bi = nb0 + 128; }
            if (Dij > a1.y && r1v.y > bs) { bs = r1v.y; bi = nb0 + 129; }
            if (Dij > a1.z && r1v.z > bs) { bs = r1v.z; bi = nb0 + 130; }
            if (Dij > a1.w && r1v.w > bs) { bs = r1v.w; bi = nb0 + 131; }
            if (Dij > a2.x && r2v.x > bs) { bs = r2v.x; bi = nb0 + 256; }
            if (Dij > a2.y && r2v.y > bs) { bs = r2v.y; bi = nb0 + 257; }
            if (Dij > a2.z && r2v.z > bs) { bs = r2v.z; bi = nb0 + 258; }
            if (Dij > a2.w && r2v.w > bs) { bs = r2v.w; bi = nb0 + 259; }
            if (Dij > a3.x && r3v.x > bs) { bs = r3v.x; bi = nb0 + 384; }
            if (Dij > a3.y && r3v.y > bs) { bs = r3v.y; bi = nb0 + 385; }
            if (Dij > a3.z && r3v.z > bs) { bs = r3v.z; bi = nb0 + 386; }
            if (Dij > a3.w && r3v.w > bs) { bs = r3v.w; bi = nb0 + 387; }

            // warp argmax, tie-break toward smaller index
            for (int off = 16; off; off >>= 1) {
                float os = __shfl_down_sync(0xffffffffu, bs, off);
                int   oi = __shfl_down_sync(0xffffffffu, bi, off);
                if (os > bs || (os == bs && oi < bi)) { bs = os; bi = oi; }
            }
            if (lane == 0 && bs >= -0.5f) {
                wloss += (double)(Dij - Drow[bi] + 3.0f);
                wcount += 1;
            }

            p = pn;
            r0v = s0; r1v = s1; r2v = s2; r3v = s3;
        }
        if (lane == 0 && wcount > 0) {
            atomicAdd(&g_loss, wloss);
            atomicAdd(&g_count, wcount);
        }
    }
    __syncthreads();

    // fused finalize: last block to arrive writes the output
    if (t == 0) {
        __threadfence();
        int prev = atomicAdd(&g_done, 1);
        if (prev == (int)gridDim.x - 1) {
            double l = atomicAdd(&g_loss, 0.0);
            int    c = atomicAdd(&g_count, 0);
            int denom = c > 0 ? c : 1;
            out[0] = (float)(l / (double)denom);
            if (out_size > 1) out[1] = (float)c;
            for (int k = 2; k < out_size; k++) out[k] = 0.0f;
        }
    }
}

extern "C" void kernel_launch(void* const* d_in, const int* in_sizes, int n_in,
                              void* d_out, int out_size) {
    const float* E   = (const float*)d_in[0];   // embeddings [512,256] f32
    const int*   lab = (const int*)d_in[1];     // labels [512] i32
    const float* R   = (const float*)d_in[2];   // rand_u [512,512,512] f32
    float* out = (float*)d_out;

    dim3 gb(NS / 32, NS / 32), tb(16, 16);
    dot_kernel<<<gb, tb>>>(E);
    pair_kernel<<<NS * 2, 256>>>(R, lab, out, out_size);
}

// round 17
// speedup vs baseline: 1.1794x; 1.0904x over previous
#include <cuda_runtime.h>
#include <cuda_bf16.h>
#include <float.h>

#define NS 512
#define EMB 256

// scratch (device globals — no allocation allowed)
__device__ float  g_G[NS * NS];     // gram matrix E·E^T
__device__ float  g_diag[NS];       // diagonal = squared norms
__device__ double g_loss;
__device__ int    g_count;
__device__ int    g_done;

// Kernel 1: G = E·E^T, 32x32 tiles, 2x2 register blocking, SYMMETRIC:
// only tiles by<=bx computed; off-diagonal tiles also write the transposed
// tile through an smem-staged coalesced store. ~47% less GEMM work.
__global__ void dot_kernel(const float* __restrict__ E) {
    const int bx = blockIdx.x, by = blockIdx.y;
    const int tx = threadIdx.x;            // 0..15
    const int ty = threadIdx.y;            // 0..15
    if (bx == 0 && by == 0 && tx == 0 && ty == 0) {
        g_loss = 0.0; g_count = 0; g_done = 0;
    }
    if (by > bx) return;                   // symmetric: skip lower triangle

    __shared__ union {
        struct { float As[32][34]; float Bs[32][34]; } k;
        float Ts[32][36];                  // transpose staging (144B rows)
    } u;
    const int tid = ty * 16 + tx;
    const int r0 = by * 32;
    const int c0 = bx * 32;
    const int lrow = tid >> 3;             // 0..31
    const int lcol = (tid & 7) * 4;        // 0,4,...,28

    float acc00 = 0.f, acc01 = 0.f, acc10 = 0.f, acc11 = 0.f;

    for (int k0 = 0; k0 < EMB; k0 += 32) {
        float4 av = *(const float4*)&E[(r0 + lrow) * EMB + k0 + lcol];
        float4 bv = *(const float4*)&E[(c0 + lrow) * EMB + k0 + lcol];
        __syncthreads();
        u.k.As[lrow][lcol + 0] = av.x; u.k.As[lrow][lcol + 1] = av.y;
        u.k.As[lrow][lcol + 2] = av.z; u.k.As[lrow][lcol + 3] = av.w;
        u.k.Bs[lrow][lcol + 0] = bv.x; u.k.Bs[lrow][lcol + 1] = bv.y;
        u.k.Bs[lrow][lcol + 2] = bv.z; u.k.Bs[lrow][lcol + 3] = bv.w;
        __syncthreads();
#pragma unroll
        for (int k = 0; k < 32; k += 2) {
            float2 a0 = *(const float2*)&u.k.As[ty][k];
            float2 a1 = *(const float2*)&u.k.As[ty + 16][k];
            float2 b0 = *(const float2*)&u.k.Bs[tx][k];
            float2 b1 = *(const float2*)&u.k.Bs[tx + 16][k];
            acc00 += a0.x * b0.x + a0.y * b0.y;
            acc01 += a0.x * b1.x + a0.y * b1.y;
            acc10 += a1.x * b0.x + a1.y * b0.y;
            acc11 += a1.x * b1.x + a1.y * b1.y;
        }
    }

    const int r_a = r0 + ty, r_b = r0 + ty + 16;
    const int c_a = c0 + tx, c_b = c0 + tx + 16;
    g_G[r_a * NS + c_a] = acc00;
    g_G[r_a * NS + c_b] = acc01;
    g_G[r_b * NS + c_a] = acc10;
    g_G[r_b * NS + c_b] = acc11;

    if (by == bx) {                        // diagonal tile: diag, no mirror
        if (r_a == c_a) g_diag[r_a] = acc00;
        if (r_b == c_b) g_diag[r_b] = acc11;
    } else {                               // mirror tile via smem transpose
        __syncthreads();                   // done reading As/Bs
        u.Ts[tx][ty]           = acc00;    // Ts[c-c0][r-r0]
        u.Ts[tx + 16][ty]      = acc01;
        u.Ts[tx][ty + 16]      = acc10;
        u.Ts[tx + 16][ty + 16] = acc11;
        __syncthreads();
        float4 v = *(const float4*)&u.Ts[lrow][lcol];
        *(float4*)&g_G[(c0 + lrow) * NS + r0 + lcol] = v;
    }
}

// Kernel 2: per-anchor block (256 thr, grid 512 — proven R12 shape).
// Prologue reordered: labels -> ballot compaction -> FIRST R prefetch
// issued -> then Drow/adj built while the prefetch flies.
__global__ void __launch_bounds__(256)
pair_kernel(const float* __restrict__ R,
            const int* __restrict__ lab,
            float* __restrict__ out, int out_size) {
    const int i = blockIdx.x;
    const int t = threadIdx.x;
    const int wid = t >> 5, lane = t & 31;

    __shared__ float Drow[NS];   // raw G row, then D row (in place)
    __shared__ float diag_s[NS];
    __shared__ float adj[NS];    // labs[n]==li ? +INF : Drow[n]-MARGIN
    __shared__ int   labs[NS];
    __shared__ int   pos[NS];    // positive-j list, ascending (ballot)
    __shared__ int   ccnt[16];

    // split prologue: independent load chains
    if (t < 128) {
        *(int4*)&labs[t * 4]     = *(const int4*)&lab[t * 4];
        *(float4*)&diag_s[t * 4] = *(const float4*)&g_diag[t * 4];
    } else {
        int n4 = (t - 128) * 4;
        *(float4*)&Drow[n4] = *(const float4*)&g_G[i * NS + n4];
    }
    __syncthreads();

    const int li = labs[i];

    // deterministic ballot compaction (needs labels only)
    const int n0 = wid * 64 + lane;
    const int n1 = n0 + 32;
    const bool b0 = (n0 > i) && (labs[n0] == li);
    const bool b1 = (n1 > i) && (labs[n1] == li);
    const unsigned m0 = __ballot_sync(0xffffffffu, b0);
    const unsigned m1 = __ballot_sync(0xffffffffu, b1);
    if (lane == 0) { ccnt[2 * wid] = __popc(m0); ccnt[2 * wid + 1] = __popc(m1); }
    __syncthreads();
    int off0 = 0, off1 = 0, mm = 0;
#pragma unroll
    for (int k = 0; k < 16; k++) {
        int c = ccnt[k];
        if (k < 2 * wid)     off0 += c;
        if (k < 2 * wid + 1) off1 += c;
        mm += c;
    }
    const unsigned below = (1u << lane) - 1u;
    if (b0) pos[off0 + __popc(m0 & below)] = n0;
    if (b1) pos[off1 + __popc(m1 & below)] = n1;
    __syncthreads();

    // issue the FIRST rand_u batch NOW — overlaps the adj build below
    const size_t ibase = (size_t)i * NS * NS;
    int p = wid;
    float4 r0v, r1v, r2v, r3v;
    if (p < mm) {
        const float4* R4 = (const float4*)(R + ibase + (size_t)pos[p] * NS);
        r0v = R4[lane]; r1v = R4[lane + 32];
        r2v = R4[lane + 64]; r3v = R4[lane + 96];
    }

    // build D row + thresholds while the prefetch flies
    const float di = diag_s[i];
    for (int n = t; n < NS; n += 256) {
        float D = di + diag_s[n] - 2.0f * Drow[n];
        Drow[n] = D;
        adj[n]  = (labs[n] == li) ? FLT_MAX : (D - 3.0f);
    }
    __syncthreads();

    double wloss = 0.0;
    int    wcount = 0;

    if (mm > 0) {
        const float4* __restrict__ adj4 = (const float4*)adj;
        const float4 a0 = adj4[lane];
        const float4 a1 = adj4[lane + 32];
        const float4 a2 = adj4[lane + 64];
        const float4 a3 = adj4[lane + 96];
        const int nb0 = lane * 4;

        while (p < mm) {
            const int pn = p + 8;
            float4 s0, s1, s2, s3;
            if (pn < mm) {                 // prefetch next pair's row
                const float4* R4n = (const float4*)(R + ibase + (size_t)pos[pn] * NS);
                s0 = R4n[lane]; s1 = R4n[lane + 32];
                s2 = R4n[lane + 64]; s3 = R4n[lane + 96];
            }
            const float Dij = Drow[pos[p]];

            float bs = -1.0f;              // scores in [0,1); -1 = none
            int   bi = 0x7fffffff;
            // n ascending within lane + strict > ⇒ first-occurrence kept
            if (Dij > a0.x && r0v.x > bs) { bs = r0v.x; bi = nb0 + 0; }
            if (Dij > a0.y && r0v.y > bs) { bs = r0v.y; bi = nb0 + 1; }
            if (Dij > a0.z && r0v.z > bs) { bs = r0v.z; bi = nb0 + 2; }
            if (Dij > a0.w && r0v.w > bs) { bs = r0v.w; bi = nb0 + 3; }
            if (Dij > a1.x && r1v.x > bs) { bs = r1v.x; bi = nb0 + 128; }
            if (Dij > a1.y && r1v.y > bs) { bs = r1v.y; bi = nb0 + 129; }
            if (Dij > a1.z && r1v.z > bs) { bs = r1v.z; bi = nb0 + 130; }
            if (Dij > a1.w && r1v.w > bs) { bs = r1v.w; bi = nb0 + 131; }
            if (Dij > a2.x && r2v.x > bs) { bs = r2v.x; bi = nb0 + 256; }
            if (Dij > a2.y && r2v.y > bs) { bs = r2v.y; bi = nb0 + 257; }
            if (Dij > a2.z && r2v.z > bs) { bs = r2v.z; bi = nb0 + 258; }
            if (Dij > a2.w && r2v.w > bs) { bs = r2v.w; bi = nb0 + 259; }
            if (Dij > a3.x && r3v.x > bs) { bs = r3v.x; bi = nb0 + 384; }
            if (Dij > a3.y && r3v.y > bs) { bs = r3v.y; bi = nb0 + 385; }
            if (Dij > a3.z && r3v.z > bs) { bs = r3v.z; bi = nb0 + 386; }
            if (Dij > a3.w && r3v.w > bs) { bs = r3v.w; bi = nb0 + 387; }

            // warp argmax, tie-break toward smaller index
            for (int off = 16; off; off >>= 1) {
                float os = __shfl_down_sync(0xffffffffu, bs, off);
                int   oi = __shfl_down_sync(0xffffffffu, bi, off);
                if (os > bs || (os == bs && oi < bi)) { bs = os; bi = oi; }
            }
            if (lane == 0 && bs >= -0.5f) {
                wloss += (double)(Dij - Drow[bi] + 3.0f);
                wcount += 1;
            }

            p = pn;
            r0v = s0; r1v = s1; r2v = s2; r3v = s3;
        }
        if (lane == 0 && wcount > 0) {
            atomicAdd(&g_loss, wloss);
            atomicAdd(&g_count, wcount);
        }
    }
    __syncthreads();

    // fused finalize: last block to arrive writes the output
    if (t == 0) {
        __threadfence();
        int prev = atomicAdd(&g_done, 1);
        if (prev == (int)gridDim.x - 1) {
            double l = atomicAdd(&g_loss, 0.0);
            int    c = atomicAdd(&g_count, 0);
            int denom = c > 0 ? c : 1;
            out[0] = (float)(l / (double)denom);
            if (out_size > 1) out[1] = (float)c;
            for (int k = 2; k < out_size; k++) out[k] = 0.0f;
        }
    }
}

extern "C" void kernel_launch(void* const* d_in, const int* in_sizes, int n_in,
                              void* d_out, int out_size) {
    const float* E   = (const float*)d_in[0];   // embeddings [512,256] f32
    const int*   lab = (const int*)d_in[1];     // labels [512] i32
    const float* R   = (const float*)d_in[2];   // rand_u [512,512,512] f32
    float* out = (float*)d_out;

    dim3 gb(NS / 32, NS / 32), tb(16, 16);
    dot_kernel<<<gb, tb>>>(E);
    pair_kernel<<<NS, 256>>>(R, lab, out, out_size);
}